// round 7
// baseline (speedup 1.0000x reference)
#include <cuda_runtime.h>
#include <cuda_bf16.h>
#include <math.h>
#include <stdint.h>

#define BB 32
#define HH 512
#define G4 2048   // 4*HH
#define TT 64
#define VV 32000
#define NBLK 128  // persistent grid for LSTM

// ------------------------- device scratch (no allocs allowed) ----------------
__device__ float g_X1[TT * BB * G4];
__device__ float g_X2[TT * BB * G4];
__device__ float g_H1[(TT + 1) * BB * HH];
__device__ float g_H2[(TT + 1) * BB * HH];
__device__ float g_logits[(size_t)TT * BB * VV];  // 262 MB
__device__ int   g_tok[TT * BB];
__device__ unsigned g_bar[2];
__device__ __nv_bfloat16 g_Wb[(size_t)VV * HH];   // bf16 W_out
__device__ __nv_bfloat16 g_Hb[TT * BB * HH];      // bf16 h2 sequence

// ------------------------- init ---------------------------------------------
__global__ void init_kernel(const int* __restrict__ inputs,
                            const int* __restrict__ targets,
                            const float* __restrict__ hiddens) {
    int i = blockIdx.x * blockDim.x + threadIdx.x;
    if (i == 0) { g_bar[0] = 0u; g_bar[1] = 0u; }
    if (i < BB * HH) {
        g_H2[i] = 0.f;
        g_H1[i] = hiddens[i];
    }
    if (i < TT * BB) {
        int t = i / BB, b = i % BB;
        g_tok[i] = (t == 0) ? inputs[b] : targets[b * TT + (t - 1)];
    }
}

// ------------------------- f32 -> bf16 conversion ----------------------------
__global__ void cvt_bf16_kernel(const float* __restrict__ src,
                                __nv_bfloat16* __restrict__ dst, int n2) {
    int i = blockIdx.x * blockDim.x + threadIdx.x;
    if (i < n2) {
        float2 v = ((const float2*)src)[i];
        ((__nv_bfloat162*)dst)[i] = __float22bfloat162_rn(v);
    }
}

// ------------------------- fp32 GEMM (X1/X2 path) ----------------------------
__global__ __launch_bounds__(256)
void gemm_nt_bias(const float* __restrict__ A, int lda,
                  const int* __restrict__ rowidx,
                  const float* __restrict__ W,
                  const float* __restrict__ bias1,
                  const float* __restrict__ bias2,
                  float* __restrict__ C, int M, int N, int K) {
    __shared__ float As[16][68];
    __shared__ float Ws[16][68];

    int tid = threadIdx.x;
    int tx = tid & 15, ty = tid >> 4;
    int m0 = blockIdx.y * 64, n0 = blockIdx.x * 64;

    float acc[4][4];
#pragma unroll
    for (int i = 0; i < 4; i++)
#pragma unroll
        for (int j = 0; j < 4; j++) acc[i][j] = 0.f;

    int lr = tid >> 2;
    int lk = (tid & 3) << 2;
    int arow = m0 + lr;
    int asrc = rowidx ? rowidx[arow] : arow;
    const float* Ap = A + (size_t)asrc * lda + lk;
    const float* Wp = W + (size_t)(n0 + lr) * K + lk;

    for (int k0 = 0; k0 < K; k0 += 16) {
        float4 av = *(const float4*)(Ap + k0);
        float4 wv = *(const float4*)(Wp + k0);
        As[lk + 0][lr] = av.x; As[lk + 1][lr] = av.y;
        As[lk + 2][lr] = av.z; As[lk + 3][lr] = av.w;
        Ws[lk + 0][lr] = wv.x; Ws[lk + 1][lr] = wv.y;
        Ws[lk + 2][lr] = wv.z; Ws[lk + 3][lr] = wv.w;
        __syncthreads();
#pragma unroll
        for (int k = 0; k < 16; k++) {
            float4 a = *(const float4*)&As[k][ty * 4];
            float4 w = *(const float4*)&Ws[k][tx * 4];
            acc[0][0] += a.x * w.x; acc[0][1] += a.x * w.y; acc[0][2] += a.x * w.z; acc[0][3] += a.x * w.w;
            acc[1][0] += a.y * w.x; acc[1][1] += a.y * w.y; acc[1][2] += a.y * w.z; acc[1][3] += a.y * w.w;
            acc[2][0] += a.z * w.x; acc[2][1] += a.z * w.y; acc[2][2] += a.z * w.z; acc[2][3] += a.z * w.w;
            acc[3][0] += a.w * w.x; acc[3][1] += a.w * w.y; acc[3][2] += a.w * w.z; acc[3][3] += a.w * w.w;
        }
        __syncthreads();
    }

#pragma unroll
    for (int i = 0; i < 4; i++) {
        int cm = m0 + ty * 4 + i;
        float* Crow = C + (size_t)cm * N;
#pragma unroll
        for (int j = 0; j < 4; j++) {
            int cn = n0 + tx * 4 + j;
            float bv = bias1[cn] + (bias2 ? bias2[cn] : 0.f);
            Crow[cn] = acc[i][j] + bv;
        }
    }
}

// ------------------------- persistent LSTM layer -----------------------------
__global__ __launch_bounds__(256)
void lstm_persistent(const float* __restrict__ X,
                     const float* __restrict__ Wh,
                     float* __restrict__ H,
                     unsigned* __restrict__ bar) {
    __shared__ float Wt[HH][16];
    __shared__ float hs[64][33];
    __shared__ float gx[4][4][32];

    const int tid = threadIdx.x;
    const int j0 = blockIdx.x * 4;

#pragma unroll
    for (int r = 0; r < 16; r++) {
        int gate = r >> 2, jj = r & 3;
        const float* src = Wh + (size_t)(gate * HH + j0 + jj) * HH;
        for (int k = tid; k < HH; k += 256) Wt[k][r] = src[k];
    }

    const int b    = tid & 31;
    const int gate = (tid >> 5) & 3;
    const int jh   = tid >> 7;
    const int w2off = (gate << 2) + (jh << 1);

    const int fb = tid & 31;
    const int fj = (tid >> 5) & 3;
    float creg = 0.f;

    const int kkld = tid & 63;
    const int rbld = tid >> 6;

    __syncthreads();

    for (int t = 0; t < TT; t++) {
        const float* Hprev = H + (size_t)t * BB * HH;
        float acc0 = 0.f, acc1 = 0.f;

        for (int c = 0; c < 8; c++) {
            const int k0 = c * 64;
#pragma unroll
            for (int rep = 0; rep < 8; rep++) {
                int r = rbld + rep * 4;
                hs[kkld][r] = Hprev[r * HH + k0 + kkld];
            }
            __syncthreads();
#pragma unroll
            for (int kk = 0; kk < 64; kk++) {
                float hv = hs[kk][b];
                float2 w2 = *(const float2*)&Wt[k0 + kk][w2off];
                acc0 += hv * w2.x;
                acc1 += hv * w2.y;
            }
            __syncthreads();
        }

        gx[gate][(jh << 1) + 0][b] = acc0;
        gx[gate][(jh << 1) + 1][b] = acc1;
        __syncthreads();

        if (tid < 128) {
            const int j = j0 + fj;
            const float* xp = X + ((size_t)t * BB + fb) * G4;
            float gi = gx[0][fj][fb] + xp[0 * HH + j];
            float gf = gx[1][fj][fb] + xp[1 * HH + j];
            float gg = gx[2][fj][fb] + xp[2 * HH + j];
            float go = gx[3][fj][fb] + xp[3 * HH + j];

            float iv = 1.f / (1.f + expf(-gi));
            float fv = 1.f / (1.f + expf(-gf));
            float tv = tanhf(gg);
            float ov = 1.f / (1.f + expf(-go));

            creg = fv * creg + iv * tv;
            H[(size_t)(t + 1) * BB * HH + fb * HH + j] = ov * tanhf(creg);
        }

        __syncthreads();
        if (tid == 0) {
            __threadfence();
            atomicAdd(bar, 1u);
            unsigned target = (unsigned)(t + 1) * (unsigned)gridDim.x;
            while (*(volatile unsigned*)bar < target) { }
            __threadfence();
        }
        __syncthreads();
    }
}

// ------------------------- bf16 mma.sync output GEMM -------------------------
// logits[m][n] = sum_k Hb[m][k] * Wb[n][k] + b_out[n]
// Block tile 128(m) x 128(n), k-chunks of 32, cp.async double buffer.
// 8 warps: wm = wid&3 (m), wn = wid>>1&? -> wn = wid>>2 in {0,1}; warp = 32m x 64n.
#define LDM_X4(r0, r1, r2, r3, addr)                                           \
    asm volatile("ldmatrix.sync.aligned.m8n8.x4.shared.b16 {%0,%1,%2,%3}, [%4];" \
                 : "=r"(r0), "=r"(r1), "=r"(r2), "=r"(r3) : "r"(addr))

#define MMA_BF16(c, a, b0, b1)                                                 \
    asm volatile(                                                              \
        "mma.sync.aligned.m16n8k16.row.col.f32.bf16.bf16.f32 "                 \
        "{%0,%1,%2,%3}, {%4,%5,%6,%7}, {%8,%9}, {%0,%1,%2,%3};"                \
        : "+f"((c)[0]), "+f"((c)[1]), "+f"((c)[2]), "+f"((c)[3])               \
        : "r"((a)[0]), "r"((a)[1]), "r"((a)[2]), "r"((a)[3]),                  \
          "r"(b0), "r"(b1))

__device__ __forceinline__ uint32_t smem_u32(const void* p) {
    uint32_t a;
    asm("{ .reg .u64 t; cvta.to.shared.u64 t, %1; cvt.u32.u64 %0, t; }"
        : "=r"(a) : "l"(p));
    return a;
}
__device__ __forceinline__ void cp_async16(uint32_t s, const void* g) {
    asm volatile("cp.async.cg.shared.global [%0], [%1], 16;"
                 :: "r"(s), "l"(g) : "memory");
}

#define TROW 80   // padded SMEM row: 40 bf16 = 80 B (conflict-free for ldmatrix)
#define TBUF (128 * TROW)

__global__ __launch_bounds__(256)
void gemm_mma(const __nv_bfloat16* __restrict__ Hb,
              const __nv_bfloat16* __restrict__ Wb,
              const float* __restrict__ b_out,
              float* __restrict__ logits) {
    __shared__ __align__(16) char As[2 * TBUF];
    __shared__ __align__(16) char Bs[2 * TBUF];

    const int tid = threadIdx.x;
    const int lid = tid & 31, wid = tid >> 5;
    const int wm = wid & 3;        // 0..3 -> m offset wm*32
    const int wn = wid >> 2;       // 0..1 -> n offset wn*64
    const int m0 = blockIdx.y * 128;   // seq rows
    const int n0 = blockIdx.x * 128;   // vocab cols

    const uint32_t sA = smem_u32(As);
    const uint32_t sB = smem_u32(Bs);

    // per-thread global/shared load coords: row = tid/4 (+64), 8 bf16 at (tid%4)*8
    const int ldr = tid >> 2;
    const int ldk = (tid & 3) << 3;
    const uint32_t soff = (uint32_t)ldr * TROW + (uint32_t)ldk * 2;

    float acc[2][8][4];
#pragma unroll
    for (int a = 0; a < 2; a++)
#pragma unroll
        for (int b = 0; b < 8; b++)
#pragma unroll
            for (int c = 0; c < 4; c++) acc[a][b][c] = 0.f;

    // issue loads for chunk c into buffer bf
    auto issue = [&](int c, int bf) {
        const int k0 = c * 32 + ldk;
        cp_async16(sA + bf * TBUF + soff,
                   Hb + (size_t)(m0 + ldr) * HH + k0);
        cp_async16(sA + bf * TBUF + soff + 64 * TROW,
                   Hb + (size_t)(m0 + ldr + 64) * HH + k0);
        cp_async16(sB + bf * TBUF + soff,
                   Wb + (size_t)(n0 + ldr) * HH + k0);
        cp_async16(sB + bf * TBUF + soff + 64 * TROW,
                   Wb + (size_t)(n0 + ldr + 64) * HH + k0);
        asm volatile("cp.async.commit_group;" ::: "memory");
    };

    issue(0, 0);

    // ldmatrix lane addressing (within warp tile)
    const int a_row = (lid & 15);          // + mt*16 + wm*32
    const int a_kh  = (lid >> 4) << 3;     // 0 or 8
    const int b_j   = lid >> 3;            // matrix id 0..3
    const int b_row = ((b_j >> 1) << 3) + (lid & 7);   // + nt16*16 + wn*64
    const int b_kh  = (b_j & 1) << 3;

    for (int c = 0; c < 16; c++) {
        const int bf = c & 1;
        if (c < 15) issue(c + 1, bf ^ 1);
        if (c < 15) asm volatile("cp.async.wait_group 1;" ::: "memory");
        else        asm volatile("cp.async.wait_group 0;" ::: "memory");
        __syncthreads();

        const uint32_t ab = sA + bf * TBUF;
        const uint32_t bb = sB + bf * TBUF;
#pragma unroll
        for (int ks = 0; ks < 32; ks += 16) {
            uint32_t afr[2][4];
#pragma unroll
            for (int mt = 0; mt < 2; mt++) {
                uint32_t addr = ab + (uint32_t)(wm * 32 + mt * 16 + a_row) * TROW
                              + (uint32_t)(ks + a_kh) * 2;
                LDM_X4(afr[mt][0], afr[mt][1], afr[mt][2], afr[mt][3], addr);
            }
#pragma unroll
            for (int nt16 = 0; nt16 < 4; nt16++) {
                uint32_t b0, b1, b2, b3;
                uint32_t addr = bb + (uint32_t)(wn * 64 + nt16 * 16 + b_row) * TROW
                              + (uint32_t)(ks + b_kh) * 2;
                LDM_X4(b0, b1, b2, b3, addr);
#pragma unroll
                for (int mt = 0; mt < 2; mt++) {
                    MMA_BF16(acc[mt][nt16 * 2 + 0], afr[mt], b0, b1);
                    MMA_BF16(acc[mt][nt16 * 2 + 1], afr[mt], b2, b3);
                }
            }
        }
        __syncthreads();
    }

    // epilogue: c0,c1 -> (row, col..col+1); c2,c3 -> (row+8, col..col+1)
    const int erow = lid >> 2;
    const int ecol = (lid & 3) << 1;
#pragma unroll
    for (int mt = 0; mt < 2; mt++) {
        const int row = m0 + wm * 32 + mt * 16 + erow;
#pragma unroll
        for (int nt = 0; nt < 8; nt++) {
            const int col = n0 + wn * 64 + nt * 8 + ecol;
            const float bv0 = b_out[col], bv1 = b_out[col + 1];
            float2 v0 = { acc[mt][nt][0] + bv0, acc[mt][nt][1] + bv1 };
            float2 v1 = { acc[mt][nt][2] + bv0, acc[mt][nt][3] + bv1 };
            *(float2*)&logits[(size_t)row * VV + col] = v0;
            *(float2*)&logits[(size_t)(row + 8) * VV + col] = v1;
        }
    }
}

// ------------------------- row softmax over V --------------------------------
__global__ __launch_bounds__(256)
void softmax_kernel(const float* __restrict__ L, float* __restrict__ out) {
    int r = blockIdx.x;
    int tid = threadIdx.x;
    const float* row = L + (size_t)r * VV;

    float m = -3.0e38f, s = 0.f;
    for (int v = tid; v < VV; v += 256) {
        float x = row[v];
        if (x > m) { s *= expf(m - x); m = x; }
        s += expf(x - m);
    }
    __shared__ float sm[256], ss[256];
    sm[tid] = m; ss[tid] = s;
    __syncthreads();
    for (int off = 128; off; off >>= 1) {
        if (tid < off) {
            float m2 = sm[tid + off], s2 = ss[tid + off];
            float M = fmaxf(sm[tid], m2);
            ss[tid] = ss[tid] * expf(sm[tid] - M) + s2 * expf(m2 - M);
            sm[tid] = M;
        }
        __syncthreads();
    }
    float M = sm[0];
    float inv = 1.f / ss[0];
    float* orow = out + (size_t)r * VV;
    for (int v = tid; v < VV; v += 256) {
        orow[v] = expf(row[v] - M) * inv;
    }
}

__global__ void copy_h1_kernel(const float* __restrict__ src, float* __restrict__ dst) {
    int i = blockIdx.x * blockDim.x + threadIdx.x;
    if (i < BB * HH) dst[i] = src[i];
}

// ------------------------- host launcher -------------------------------------
static float* sym_f(const void* sym) {
    void* p = nullptr; cudaGetSymbolAddress(&p, sym); return (float*)p;
}
static int* sym_i(const void* sym) {
    void* p = nullptr; cudaGetSymbolAddress(&p, sym); return (int*)p;
}
static unsigned* sym_u(const void* sym) {
    void* p = nullptr; cudaGetSymbolAddress(&p, sym); return (unsigned*)p;
}
static __nv_bfloat16* sym_b(const void* sym) {
    void* p = nullptr; cudaGetSymbolAddress(&p, sym); return (__nv_bfloat16*)p;
}

extern "C" void kernel_launch(void* const* d_in, const int* in_sizes, int n_in,
                              void* d_out, int out_size) {
    const int*   inputs  = (const int*)d_in[0];
    const float* hiddens = (const float*)d_in[1];
    const int*   targets = (const int*)d_in[2];
    const float* emb   = (const float*)d_in[4];
    const float* W_ih1 = (const float*)d_in[5];
    const float* W_hh1 = (const float*)d_in[6];
    const float* b_ih1 = (const float*)d_in[7];
    const float* b_hh1 = (const float*)d_in[8];
    const float* W_ih2 = (const float*)d_in[9];
    const float* W_hh2 = (const float*)d_in[10];
    const float* b_ih2 = (const float*)d_in[11];
    const float* b_hh2 = (const float*)d_in[12];
    const float* W_out = (const float*)d_in[13];
    const float* b_out = (const float*)d_in[14];
    float* out = (float*)d_out;

    float* X1 = sym_f(g_X1);
    float* X2 = sym_f(g_X2);
    float* H1 = sym_f(g_H1);
    float* H2 = sym_f(g_H2);
    float* LG = sym_f(g_logits);
    int*   TK = sym_i(g_tok);
    unsigned* BAR = sym_u(g_bar);
    __nv_bfloat16* Wb = sym_b(g_Wb);
    __nv_bfloat16* Hb = sym_b(g_Hb);

    // 1) init
    init_kernel<<<(BB * HH + 255) / 256, 256>>>(inputs, targets, hiddens);

    // 1b) W_out -> bf16 (independent of everything else)
    cvt_bf16_kernel<<<(VV * HH / 2 + 255) / 256, 256>>>(W_out, Wb, VV * HH / 2);

    // 2) X1 = gather(emb, tok) @ W_ih1^T + biases
    gemm_nt_bias<<<dim3(G4 / 64, (TT * BB) / 64), 256>>>(
        emb, HH, TK, W_ih1, b_ih1, b_hh1, X1, TT * BB, G4, HH);

    // 3) layer-1 recurrence (persistent)
    lstm_persistent<<<NBLK, 256>>>(X1, W_hh1, H1, BAR + 0);

    // 4) X2 = H1[1..64] @ W_ih2^T + biases
    gemm_nt_bias<<<dim3(G4 / 64, (TT * BB) / 64), 256>>>(
        H1 + BB * HH, HH, nullptr, W_ih2, b_ih2, b_hh2, X2, TT * BB, G4, HH);

    // 5) layer-2 recurrence
    lstm_persistent<<<NBLK, 256>>>(X2, W_hh2, H2, BAR + 1);

    // 5b) h2 sequence -> bf16
    cvt_bf16_kernel<<<(TT * BB * HH / 2 + 255) / 256, 256>>>(
        H2 + BB * HH, Hb, TT * BB * HH / 2);

    // 6) logits = h2 @ W_out^T + b_out  via bf16 mma.sync tensor cores
    gemm_mma<<<dim3(VV / 128, (TT * BB) / 128), 256>>>(Hb, Wb, b_out, LG);

    // 7) softmax
    softmax_kernel<<<TT * BB, 256>>>(LG, out);

    // 8) final h1
    long long tbv = (long long)TT * BB * VV;
    if ((long long)out_size >= tbv + (long long)BB * HH) {
        copy_h1_kernel<<<(BB * HH + 255) / 256, 256>>>(H1 + (size_t)TT * BB * HH,
                                                       out + tbv);
    }
}

// round 8
// speedup vs baseline: 1.0012x; 1.0012x over previous
#include <cuda_runtime.h>
#include <cuda_bf16.h>
#include <math.h>
#include <stdint.h>

#define BB 32
#define HH 512
#define G4 2048   // 4*HH
#define TT 64
#define VV 32000
#define NBLK 128  // persistent grid for LSTM

// ------------------------- device scratch (no allocs allowed) ----------------
__device__ float g_X1[TT * BB * G4];
__device__ float g_X2[TT * BB * G4];
__device__ float g_H1[(TT + 1) * BB * HH];
__device__ float g_H2[(TT + 1) * BB * HH];
__device__ float g_logits[(size_t)TT * BB * VV];  // 262 MB
__device__ int   g_tok[TT * BB];
__device__ unsigned g_bar[2];
__device__ __nv_bfloat16 g_Wb[(size_t)VV * HH];   // bf16 W_out
__device__ __nv_bfloat16 g_Hb[TT * BB * HH];      // bf16 h2 sequence

// ------------------------- init ---------------------------------------------
__global__ void init_kernel(const int* __restrict__ inputs,
                            const int* __restrict__ targets,
                            const float* __restrict__ hiddens) {
    int i = blockIdx.x * blockDim.x + threadIdx.x;
    if (i == 0) { g_bar[0] = 0u; g_bar[1] = 0u; }
    if (i < BB * HH) {
        g_H2[i] = 0.f;
        g_H1[i] = hiddens[i];
    }
    if (i < TT * BB) {
        int t = i / BB, b = i % BB;
        g_tok[i] = (t == 0) ? inputs[b] : targets[b * TT + (t - 1)];
    }
}

// ------------------------- f32 -> bf16 conversion ----------------------------
__global__ void cvt_bf16_kernel(const float* __restrict__ src,
                                __nv_bfloat16* __restrict__ dst, int n2) {
    int i = blockIdx.x * blockDim.x + threadIdx.x;
    if (i < n2) {
        float2 v = ((const float2*)src)[i];
        ((__nv_bfloat162*)dst)[i] = __float22bfloat162_rn(v);
    }
}

// ------------------------- fp32 GEMM (X1/X2 path) ----------------------------
__global__ __launch_bounds__(256)
void gemm_nt_bias(const float* __restrict__ A, int lda,
                  const int* __restrict__ rowidx,
                  const float* __restrict__ W,
                  const float* __restrict__ bias1,
                  const float* __restrict__ bias2,
                  float* __restrict__ C, int M, int N, int K) {
    __shared__ float As[16][68];
    __shared__ float Ws[16][68];

    int tid = threadIdx.x;
    int tx = tid & 15, ty = tid >> 4;
    int m0 = blockIdx.y * 64, n0 = blockIdx.x * 64;

    float acc[4][4];
#pragma unroll
    for (int i = 0; i < 4; i++)
#pragma unroll
        for (int j = 0; j < 4; j++) acc[i][j] = 0.f;

    int lr = tid >> 2;
    int lk = (tid & 3) << 2;
    int arow = m0 + lr;
    int asrc = rowidx ? rowidx[arow] : arow;
    const float* Ap = A + (size_t)asrc * lda + lk;
    const float* Wp = W + (size_t)(n0 + lr) * K + lk;

    for (int k0 = 0; k0 < K; k0 += 16) {
        float4 av = *(const float4*)(Ap + k0);
        float4 wv = *(const float4*)(Wp + k0);
        As[lk + 0][lr] = av.x; As[lk + 1][lr] = av.y;
        As[lk + 2][lr] = av.z; As[lk + 3][lr] = av.w;
        Ws[lk + 0][lr] = wv.x; Ws[lk + 1][lr] = wv.y;
        Ws[lk + 2][lr] = wv.z; Ws[lk + 3][lr] = wv.w;
        __syncthreads();
#pragma unroll
        for (int k = 0; k < 16; k++) {
            float4 a = *(const float4*)&As[k][ty * 4];
            float4 w = *(const float4*)&Ws[k][tx * 4];
            acc[0][0] += a.x * w.x; acc[0][1] += a.x * w.y; acc[0][2] += a.x * w.z; acc[0][3] += a.x * w.w;
            acc[1][0] += a.y * w.x; acc[1][1] += a.y * w.y; acc[1][2] += a.y * w.z; acc[1][3] += a.y * w.w;
            acc[2][0] += a.z * w.x; acc[2][1] += a.z * w.y; acc[2][2] += a.z * w.z; acc[2][3] += a.z * w.w;
            acc[3][0] += a.w * w.x; acc[3][1] += a.w * w.y; acc[3][2] += a.w * w.z; acc[3][3] += a.w * w.w;
        }
        __syncthreads();
    }

#pragma unroll
    for (int i = 0; i < 4; i++) {
        int cm = m0 + ty * 4 + i;
        float* Crow = C + (size_t)cm * N;
#pragma unroll
        for (int j = 0; j < 4; j++) {
            int cn = n0 + tx * 4 + j;
            float bv = bias1[cn] + (bias2 ? bias2[cn] : 0.f);
            Crow[cn] = acc[i][j] + bv;
        }
    }
}

// ------------------------- persistent LSTM layer -----------------------------
__global__ __launch_bounds__(256)
void lstm_persistent(const float* __restrict__ X,
                     const float* __restrict__ Wh,
                     float* __restrict__ H,
                     unsigned* __restrict__ bar) {
    __shared__ float Wt[HH][16];
    __shared__ float hs[64][33];
    __shared__ float gx[4][4][32];

    const int tid = threadIdx.x;
    const int j0 = blockIdx.x * 4;

#pragma unroll
    for (int r = 0; r < 16; r++) {
        int gate = r >> 2, jj = r & 3;
        const float* src = Wh + (size_t)(gate * HH + j0 + jj) * HH;
        for (int k = tid; k < HH; k += 256) Wt[k][r] = src[k];
    }

    const int b    = tid & 31;
    const int gate = (tid >> 5) & 3;
    const int jh   = tid >> 7;
    const int w2off = (gate << 2) + (jh << 1);

    const int fb = tid & 31;
    const int fj = (tid >> 5) & 3;
    float creg = 0.f;

    const int kkld = tid & 63;
    const int rbld = tid >> 6;

    __syncthreads();

    for (int t = 0; t < TT; t++) {
        const float* Hprev = H + (size_t)t * BB * HH;
        float acc0 = 0.f, acc1 = 0.f;

        for (int c = 0; c < 8; c++) {
            const int k0 = c * 64;
#pragma unroll
            for (int rep = 0; rep < 8; rep++) {
                int r = rbld + rep * 4;
                hs[kkld][r] = Hprev[r * HH + k0 + kkld];
            }
            __syncthreads();
#pragma unroll
            for (int kk = 0; kk < 64; kk++) {
                float hv = hs[kk][b];
                float2 w2 = *(const float2*)&Wt[k0 + kk][w2off];
                acc0 += hv * w2.x;
                acc1 += hv * w2.y;
            }
            __syncthreads();
        }

        gx[gate][(jh << 1) + 0][b] = acc0;
        gx[gate][(jh << 1) + 1][b] = acc1;
        __syncthreads();

        if (tid < 128) {
            const int j = j0 + fj;
            const float* xp = X + ((size_t)t * BB + fb) * G4;
            float gi = gx[0][fj][fb] + xp[0 * HH + j];
            float gf = gx[1][fj][fb] + xp[1 * HH + j];
            float gg = gx[2][fj][fb] + xp[2 * HH + j];
            float go = gx[3][fj][fb] + xp[3 * HH + j];

            float iv = 1.f / (1.f + expf(-gi));
            float fv = 1.f / (1.f + expf(-gf));
            float tv = tanhf(gg);
            float ov = 1.f / (1.f + expf(-go));

            creg = fv * creg + iv * tv;
            H[(size_t)(t + 1) * BB * HH + fb * HH + j] = ov * tanhf(creg);
        }

        __syncthreads();
        if (tid == 0) {
            __threadfence();
            atomicAdd(bar, 1u);
            unsigned target = (unsigned)(t + 1) * (unsigned)gridDim.x;
            while (*(volatile unsigned*)bar < target) { }
            __threadfence();
        }
        __syncthreads();
    }
}

// ------------------------- bf16 mma.sync output GEMM -------------------------
// logits[m][n] = sum_k Hb[m][k] * Wb[n][k] + b_out[n]
// Block tile 128(m) x 128(n), k-chunks of 32, cp.async double buffer.
// 8 warps: wm = wid&3 (m), wn = wid>>1&? -> wn = wid>>2 in {0,1}; warp = 32m x 64n.
#define LDM_X4(r0, r1, r2, r3, addr)                                           \
    asm volatile("ldmatrix.sync.aligned.m8n8.x4.shared.b16 {%0,%1,%2,%3}, [%4];" \
                 : "=r"(r0), "=r"(r1), "=r"(r2), "=r"(r3) : "r"(addr))

#define MMA_BF16(c, a, b0, b1)                                                 \
    asm volatile(                                                              \
        "mma.sync.aligned.m16n8k16.row.col.f32.bf16.bf16.f32 "                 \
        "{%0,%1,%2,%3}, {%4,%5,%6,%7}, {%8,%9}, {%0,%1,%2,%3};"                \
        : "+f"((c)[0]), "+f"((c)[1]), "+f"((c)[2]), "+f"((c)[3])               \
        : "r"((a)[0]), "r"((a)[1]), "r"((a)[2]), "r"((a)[3]),                  \
          "r"(b0), "r"(b1))

__device__ __forceinline__ uint32_t smem_u32(const void* p) {
    uint32_t a;
    asm("{ .reg .u64 t; cvta.to.shared.u64 t, %1; cvt.u32.u64 %0, t; }"
        : "=r"(a) : "l"(p));
    return a;
}
__device__ __forceinline__ void cp_async16(uint32_t s, const void* g) {
    asm volatile("cp.async.cg.shared.global [%0], [%1], 16;"
                 :: "r"(s), "l"(g) : "memory");
}

#define TROW 80   // padded SMEM row: 40 bf16 = 80 B (conflict-free for ldmatrix)
#define TBUF (128 * TROW)

__global__ __launch_bounds__(256)
void gemm_mma(const __nv_bfloat16* __restrict__ Hb,
              const __nv_bfloat16* __restrict__ Wb,
              const float* __restrict__ b_out,
              float* __restrict__ logits) {
    __shared__ __align__(16) char As[2 * TBUF];
    __shared__ __align__(16) char Bs[2 * TBUF];

    const int tid = threadIdx.x;
    const int lid = tid & 31, wid = tid >> 5;
    const int wm = wid & 3;        // 0..3 -> m offset wm*32
    const int wn = wid >> 2;       // 0..1 -> n offset wn*64
    const int m0 = blockIdx.y * 128;   // seq rows
    const int n0 = blockIdx.x * 128;   // vocab cols

    const uint32_t sA = smem_u32(As);
    const uint32_t sB = smem_u32(Bs);

    // per-thread global/shared load coords: row = tid/4 (+64), 8 bf16 at (tid%4)*8
    const int ldr = tid >> 2;
    const int ldk = (tid & 3) << 3;
    const uint32_t soff = (uint32_t)ldr * TROW + (uint32_t)ldk * 2;

    float acc[2][8][4];
#pragma unroll
    for (int a = 0; a < 2; a++)
#pragma unroll
        for (int b = 0; b < 8; b++)
#pragma unroll
            for (int c = 0; c < 4; c++) acc[a][b][c] = 0.f;

    // issue loads for chunk c into buffer bf
    auto issue = [&](int c, int bf) {
        const int k0 = c * 32 + ldk;
        cp_async16(sA + bf * TBUF + soff,
                   Hb + (size_t)(m0 + ldr) * HH + k0);
        cp_async16(sA + bf * TBUF + soff + 64 * TROW,
                   Hb + (size_t)(m0 + ldr + 64) * HH + k0);
        cp_async16(sB + bf * TBUF + soff,
                   Wb + (size_t)(n0 + ldr) * HH + k0);
        cp_async16(sB + bf * TBUF + soff + 64 * TROW,
                   Wb + (size_t)(n0 + ldr + 64) * HH + k0);
        asm volatile("cp.async.commit_group;" ::: "memory");
    };

    issue(0, 0);

    // ldmatrix lane addressing (within warp tile)
    const int a_row = (lid & 15);          // + mt*16 + wm*32
    const int a_kh  = (lid >> 4) << 3;     // 0 or 8
    const int b_j   = lid >> 3;            // matrix id 0..3
    const int b_row = ((b_j >> 1) << 3) + (lid & 7);   // + nt16*16 + wn*64
    const int b_kh  = (b_j & 1) << 3;

    for (int c = 0; c < 16; c++) {
        const int bf = c & 1;
        if (c < 15) issue(c + 1, bf ^ 1);
        if (c < 15) asm volatile("cp.async.wait_group 1;" ::: "memory");
        else        asm volatile("cp.async.wait_group 0;" ::: "memory");
        __syncthreads();

        const uint32_t ab = sA + bf * TBUF;
        const uint32_t bb = sB + bf * TBUF;
#pragma unroll
        for (int ks = 0; ks < 32; ks += 16) {
            uint32_t afr[2][4];
#pragma unroll
            for (int mt = 0; mt < 2; mt++) {
                uint32_t addr = ab + (uint32_t)(wm * 32 + mt * 16 + a_row) * TROW
                              + (uint32_t)(ks + a_kh) * 2;
                LDM_X4(afr[mt][0], afr[mt][1], afr[mt][2], afr[mt][3], addr);
            }
#pragma unroll
            for (int nt16 = 0; nt16 < 4; nt16++) {
                uint32_t b0, b1, b2, b3;
                uint32_t addr = bb + (uint32_t)(wn * 64 + nt16 * 16 + b_row) * TROW
                              + (uint32_t)(ks + b_kh) * 2;
                LDM_X4(b0, b1, b2, b3, addr);
#pragma unroll
                for (int mt = 0; mt < 2; mt++) {
                    MMA_BF16(acc[mt][nt16 * 2 + 0], afr[mt], b0, b1);
                    MMA_BF16(acc[mt][nt16 * 2 + 1], afr[mt], b2, b3);
                }
            }
        }
        __syncthreads();
    }

    // epilogue: c0,c1 -> (row, col..col+1); c2,c3 -> (row+8, col..col+1)
    const int erow = lid >> 2;
    const int ecol = (lid & 3) << 1;
#pragma unroll
    for (int mt = 0; mt < 2; mt++) {
        const int row = m0 + wm * 32 + mt * 16 + erow;
#pragma unroll
        for (int nt = 0; nt < 8; nt++) {
            const int col = n0 + wn * 64 + nt * 8 + ecol;
            const float bv0 = b_out[col], bv1 = b_out[col + 1];
            float2 v0 = { acc[mt][nt][0] + bv0, acc[mt][nt][1] + bv1 };
            float2 v1 = { acc[mt][nt][2] + bv0, acc[mt][nt][3] + bv1 };
            *(float2*)&logits[(size_t)row * VV + col] = v0;
            *(float2*)&logits[(size_t)(row + 8) * VV + col] = v1;
        }
    }
}

// ------------------------- row softmax over V --------------------------------
__global__ __launch_bounds__(256)
void softmax_kernel(const float* __restrict__ L, float* __restrict__ out) {
    int r = blockIdx.x;
    int tid = threadIdx.x;
    const float* row = L + (size_t)r * VV;

    float m = -3.0e38f, s = 0.f;
    for (int v = tid; v < VV; v += 256) {
        float x = row[v];
        if (x > m) { s *= expf(m - x); m = x; }
        s += expf(x - m);
    }
    __shared__ float sm[256], ss[256];
    sm[tid] = m; ss[tid] = s;
    __syncthreads();
    for (int off = 128; off; off >>= 1) {
        if (tid < off) {
            float m2 = sm[tid + off], s2 = ss[tid + off];
            float M = fmaxf(sm[tid], m2);
            ss[tid] = ss[tid] * expf(sm[tid] - M) + s2 * expf(m2 - M);
            sm[tid] = M;
        }
        __syncthreads();
    }
    float M = sm[0];
    float inv = 1.f / ss[0];
    float* orow = out + (size_t)r * VV;
    for (int v = tid; v < VV; v += 256) {
        orow[v] = expf(row[v] - M) * inv;
    }
}

__global__ void copy_h1_kernel(const float* __restrict__ src, float* __restrict__ dst) {
    int i = blockIdx.x * blockDim.x + threadIdx.x;
    if (i < BB * HH) dst[i] = src[i];
}

// ------------------------- host launcher -------------------------------------
static float* sym_f(const void* sym) {
    void* p = nullptr; cudaGetSymbolAddress(&p, sym); return (float*)p;
}
static int* sym_i(const void* sym) {
    void* p = nullptr; cudaGetSymbolAddress(&p, sym); return (int*)p;
}
static unsigned* sym_u(const void* sym) {
    void* p = nullptr; cudaGetSymbolAddress(&p, sym); return (unsigned*)p;
}
static __nv_bfloat16* sym_b(const void* sym) {
    void* p = nullptr; cudaGetSymbolAddress(&p, sym); return (__nv_bfloat16*)p;
}

extern "C" void kernel_launch(void* const* d_in, const int* in_sizes, int n_in,
                              void* d_out, int out_size) {
    const int*   inputs  = (const int*)d_in[0];
    const float* hiddens = (const float*)d_in[1];
    const int*   targets = (const int*)d_in[2];
    const float* emb   = (const float*)d_in[4];
    const float* W_ih1 = (const float*)d_in[5];
    const float* W_hh1 = (const float*)d_in[6];
    const float* b_ih1 = (const float*)d_in[7];
    const float* b_hh1 = (const float*)d_in[8];
    const float* W_ih2 = (const float*)d_in[9];
    const float* W_hh2 = (const float*)d_in[10];
    const float* b_ih2 = (const float*)d_in[11];
    const float* b_hh2 = (const float*)d_in[12];
    const float* W_out = (const float*)d_in[13];
    const float* b_out = (const float*)d_in[14];
    float* out = (float*)d_out;

    float* X1 = sym_f(g_X1);
    float* X2 = sym_f(g_X2);
    float* H1 = sym_f(g_H1);
    float* H2 = sym_f(g_H2);
    float* LG = sym_f(g_logits);
    int*   TK = sym_i(g_tok);
    unsigned* BAR = sym_u(g_bar);
    __nv_bfloat16* Wb = sym_b(g_Wb);
    __nv_bfloat16* Hb = sym_b(g_Hb);

    // 1) init
    init_kernel<<<(BB * HH + 255) / 256, 256>>>(inputs, targets, hiddens);

    // 1b) W_out -> bf16 (independent of everything else)
    cvt_bf16_kernel<<<(VV * HH / 2 + 255) / 256, 256>>>(W_out, Wb, VV * HH / 2);

    // 2) X1 = gather(emb, tok) @ W_ih1^T + biases
    gemm_nt_bias<<<dim3(G4 / 64, (TT * BB) / 64), 256>>>(
        emb, HH, TK, W_ih1, b_ih1, b_hh1, X1, TT * BB, G4, HH);

    // 3) layer-1 recurrence (persistent)
    lstm_persistent<<<NBLK, 256>>>(X1, W_hh1, H1, BAR + 0);

    // 4) X2 = H1[1..64] @ W_ih2^T + biases
    gemm_nt_bias<<<dim3(G4 / 64, (TT * BB) / 64), 256>>>(
        H1 + BB * HH, HH, nullptr, W_ih2, b_ih2, b_hh2, X2, TT * BB, G4, HH);

    // 5) layer-2 recurrence
    lstm_persistent<<<NBLK, 256>>>(X2, W_hh2, H2, BAR + 1);

    // 5b) h2 sequence -> bf16
    cvt_bf16_kernel<<<(TT * BB * HH / 2 + 255) / 256, 256>>>(
        H2 + BB * HH, Hb, TT * BB * HH / 2);

    // 6) logits = h2 @ W_out^T + b_out  via bf16 mma.sync tensor cores
    gemm_mma<<<dim3(VV / 128, (TT * BB) / 128), 256>>>(Hb, Wb, b_out, LG);

    // 7) softmax
    softmax_kernel<<<TT * BB, 256>>>(LG, out);

    // 8) final h1
    long long tbv = (long long)TT * BB * VV;
    if ((long long)out_size >= tbv + (long long)BB * HH) {
        copy_h1_kernel<<<(BB * HH + 255) / 256, 256>>>(H1 + (size_t)TT * BB * HH,
                                                       out + tbv);
    }
}

// round 9
// speedup vs baseline: 1.0012x; 1.0000x over previous
#include <cuda_runtime.h>
#include <cuda_bf16.h>
#include <math.h>
#include <stdint.h>

#define BB 32
#define HH 512
#define G4 2048   // 4*HH
#define TT 64
#define VV 32000
#define NBLK 128  // persistent grid for LSTM

// ------------------------- device scratch (no allocs allowed) ----------------
__device__ float g_X1[TT * BB * G4];
__device__ float g_X2[TT * BB * G4];
__device__ float g_H1[(TT + 1) * BB * HH];
__device__ float g_H2[(TT + 1) * BB * HH];
__device__ float g_logits[(size_t)TT * BB * VV];  // 262 MB
__device__ int   g_tok[TT * BB];
__device__ unsigned g_bar[2];
__device__ __nv_bfloat16 g_Wb[(size_t)VV * HH];   // bf16 W_out
__device__ __nv_bfloat16 g_Hb[TT * BB * HH];      // bf16 h2 sequence

// ------------------------- init ---------------------------------------------
__global__ void init_kernel(const int* __restrict__ inputs,
                            const int* __restrict__ targets,
                            const float* __restrict__ hiddens) {
    int i = blockIdx.x * blockDim.x + threadIdx.x;
    if (i == 0) { g_bar[0] = 0u; g_bar[1] = 0u; }
    if (i < BB * HH) {
        g_H2[i] = 0.f;
        g_H1[i] = hiddens[i];
    }
    if (i < TT * BB) {
        int t = i / BB, b = i % BB;
        g_tok[i] = (t == 0) ? inputs[b] : targets[b * TT + (t - 1)];
    }
}

// ------------------------- f32 -> bf16 conversion ----------------------------
__global__ void cvt_bf16_kernel(const float* __restrict__ src,
                                __nv_bfloat16* __restrict__ dst, int n2) {
    int i = blockIdx.x * blockDim.x + threadIdx.x;
    if (i < n2) {
        float2 v = ((const float2*)src)[i];
        ((__nv_bfloat162*)dst)[i] = __float22bfloat162_rn(v);
    }
}

// ------------------------- fp32 GEMM (X1/X2 path) ----------------------------
__global__ __launch_bounds__(256)
void gemm_nt_bias(const float* __restrict__ A, int lda,
                  const int* __restrict__ rowidx,
                  const float* __restrict__ W,
                  const float* __restrict__ bias1,
                  const float* __restrict__ bias2,
                  float* __restrict__ C, int M, int N, int K) {
    __shared__ float As[16][68];
    __shared__ float Ws[16][68];

    int tid = threadIdx.x;
    int tx = tid & 15, ty = tid >> 4;
    int m0 = blockIdx.y * 64, n0 = blockIdx.x * 64;

    float acc[4][4];
#pragma unroll
    for (int i = 0; i < 4; i++)
#pragma unroll
        for (int j = 0; j < 4; j++) acc[i][j] = 0.f;

    int lr = tid >> 2;
    int lk = (tid & 3) << 2;
    int arow = m0 + lr;
    int asrc = rowidx ? rowidx[arow] : arow;
    const float* Ap = A + (size_t)asrc * lda + lk;
    const float* Wp = W + (size_t)(n0 + lr) * K + lk;

    for (int k0 = 0; k0 < K; k0 += 16) {
        float4 av = *(const float4*)(Ap + k0);
        float4 wv = *(const float4*)(Wp + k0);
        As[lk + 0][lr] = av.x; As[lk + 1][lr] = av.y;
        As[lk + 2][lr] = av.z; As[lk + 3][lr] = av.w;
        Ws[lk + 0][lr] = wv.x; Ws[lk + 1][lr] = wv.y;
        Ws[lk + 2][lr] = wv.z; Ws[lk + 3][lr] = wv.w;
        __syncthreads();
#pragma unroll
        for (int k = 0; k < 16; k++) {
            float4 a = *(const float4*)&As[k][ty * 4];
            float4 w = *(const float4*)&Ws[k][tx * 4];
            acc[0][0] += a.x * w.x; acc[0][1] += a.x * w.y; acc[0][2] += a.x * w.z; acc[0][3] += a.x * w.w;
            acc[1][0] += a.y * w.x; acc[1][1] += a.y * w.y; acc[1][2] += a.y * w.z; acc[1][3] += a.y * w.w;
            acc[2][0] += a.z * w.x; acc[2][1] += a.z * w.y; acc[2][2] += a.z * w.z; acc[2][3] += a.z * w.w;
            acc[3][0] += a.w * w.x; acc[3][1] += a.w * w.y; acc[3][2] += a.w * w.z; acc[3][3] += a.w * w.w;
        }
        __syncthreads();
    }

#pragma unroll
    for (int i = 0; i < 4; i++) {
        int cm = m0 + ty * 4 + i;
        float* Crow = C + (size_t)cm * N;
#pragma unroll
        for (int j = 0; j < 4; j++) {
            int cn = n0 + tx * 4 + j;
            float bv = bias1[cn] + (bias2 ? bias2[cn] : 0.f);
            Crow[cn] = acc[i][j] + bv;
        }
    }
}

// ------------------------- persistent LSTM layer -----------------------------
__global__ __launch_bounds__(256)
void lstm_persistent(const float* __restrict__ X,
                     const float* __restrict__ Wh,
                     float* __restrict__ H,
                     unsigned* __restrict__ bar) {
    __shared__ float Wt[HH][16];
    __shared__ float hs[64][33];
    __shared__ float gx[4][4][32];

    const int tid = threadIdx.x;
    const int j0 = blockIdx.x * 4;

#pragma unroll
    for (int r = 0; r < 16; r++) {
        int gate = r >> 2, jj = r & 3;
        const float* src = Wh + (size_t)(gate * HH + j0 + jj) * HH;
        for (int k = tid; k < HH; k += 256) Wt[k][r] = src[k];
    }

    const int b    = tid & 31;
    const int gate = (tid >> 5) & 3;
    const int jh   = tid >> 7;
    const int w2off = (gate << 2) + (jh << 1);

    const int fb = tid & 31;
    const int fj = (tid >> 5) & 3;
    float creg = 0.f;

    const int kkld = tid & 63;
    const int rbld = tid >> 6;

    __syncthreads();

    for (int t = 0; t < TT; t++) {
        const float* Hprev = H + (size_t)t * BB * HH;
        float acc0 = 0.f, acc1 = 0.f;

        for (int c = 0; c < 8; c++) {
            const int k0 = c * 64;
#pragma unroll
            for (int rep = 0; rep < 8; rep++) {
                int r = rbld + rep * 4;
                hs[kkld][r] = Hprev[r * HH + k0 + kkld];
            }
            __syncthreads();
#pragma unroll
            for (int kk = 0; kk < 64; kk++) {
                float hv = hs[kk][b];
                float2 w2 = *(const float2*)&Wt[k0 + kk][w2off];
                acc0 += hv * w2.x;
                acc1 += hv * w2.y;
            }
            __syncthreads();
        }

        gx[gate][(jh << 1) + 0][b] = acc0;
        gx[gate][(jh << 1) + 1][b] = acc1;
        __syncthreads();

        if (tid < 128) {
            const int j = j0 + fj;
            const float* xp = X + ((size_t)t * BB + fb) * G4;
            float gi = gx[0][fj][fb] + xp[0 * HH + j];
            float gf = gx[1][fj][fb] + xp[1 * HH + j];
            float gg = gx[2][fj][fb] + xp[2 * HH + j];
            float go = gx[3][fj][fb] + xp[3 * HH + j];

            float iv = 1.f / (1.f + expf(-gi));
            float fv = 1.f / (1.f + expf(-gf));
            float tv = tanhf(gg);
            float ov = 1.f / (1.f + expf(-go));

            creg = fv * creg + iv * tv;
            H[(size_t)(t + 1) * BB * HH + fb * HH + j] = ov * tanhf(creg);
        }

        __syncthreads();
        if (tid == 0) {
            __threadfence();
            atomicAdd(bar, 1u);
            unsigned target = (unsigned)(t + 1) * (unsigned)gridDim.x;
            while (*(volatile unsigned*)bar < target) { }
            __threadfence();
        }
        __syncthreads();
    }
}

// ------------------------- bf16 mma.sync output GEMM -------------------------
// logits[m][n] = sum_k Hb[m][k] * Wb[n][k] + b_out[n]
// Block tile 128(m) x 128(n), k-chunks of 32, cp.async double buffer.
// 8 warps: wm = wid&3 (m), wn = wid>>1&? -> wn = wid>>2 in {0,1}; warp = 32m x 64n.
#define LDM_X4(r0, r1, r2, r3, addr)                                           \
    asm volatile("ldmatrix.sync.aligned.m8n8.x4.shared.b16 {%0,%1,%2,%3}, [%4];" \
                 : "=r"(r0), "=r"(r1), "=r"(r2), "=r"(r3) : "r"(addr))

#define MMA_BF16(c, a, b0, b1)                                                 \
    asm volatile(                                                              \
        "mma.sync.aligned.m16n8k16.row.col.f32.bf16.bf16.f32 "                 \
        "{%0,%1,%2,%3}, {%4,%5,%6,%7}, {%8,%9}, {%0,%1,%2,%3};"                \
        : "+f"((c)[0]), "+f"((c)[1]), "+f"((c)[2]), "+f"((c)[3])               \
        : "r"((a)[0]), "r"((a)[1]), "r"((a)[2]), "r"((a)[3]),                  \
          "r"(b0), "r"(b1))

__device__ __forceinline__ uint32_t smem_u32(const void* p) {
    uint32_t a;
    asm("{ .reg .u64 t; cvta.to.shared.u64 t, %1; cvt.u32.u64 %0, t; }"
        : "=r"(a) : "l"(p));
    return a;
}
__device__ __forceinline__ void cp_async16(uint32_t s, const void* g) {
    asm volatile("cp.async.cg.shared.global [%0], [%1], 16;"
                 :: "r"(s), "l"(g) : "memory");
}

#define TROW 80   // padded SMEM row: 40 bf16 = 80 B (conflict-free for ldmatrix)
#define TBUF (128 * TROW)

__global__ __launch_bounds__(256)
void gemm_mma(const __nv_bfloat16* __restrict__ Hb,
              const __nv_bfloat16* __restrict__ Wb,
              const float* __restrict__ b_out,
              float* __restrict__ logits) {
    __shared__ __align__(16) char As[2 * TBUF];
    __shared__ __align__(16) char Bs[2 * TBUF];

    const int tid = threadIdx.x;
    const int lid = tid & 31, wid = tid >> 5;
    const int wm = wid & 3;        // 0..3 -> m offset wm*32
    const int wn = wid >> 2;       // 0..1 -> n offset wn*64
    const int m0 = blockIdx.y * 128;   // seq rows
    const int n0 = blockIdx.x * 128;   // vocab cols

    const uint32_t sA = smem_u32(As);
    const uint32_t sB = smem_u32(Bs);

    // per-thread global/shared load coords: row = tid/4 (+64), 8 bf16 at (tid%4)*8
    const int ldr = tid >> 2;
    const int ldk = (tid & 3) << 3;
    const uint32_t soff = (uint32_t)ldr * TROW + (uint32_t)ldk * 2;

    float acc[2][8][4];
#pragma unroll
    for (int a = 0; a < 2; a++)
#pragma unroll
        for (int b = 0; b < 8; b++)
#pragma unroll
            for (int c = 0; c < 4; c++) acc[a][b][c] = 0.f;

    // issue loads for chunk c into buffer bf
    auto issue = [&](int c, int bf) {
        const int k0 = c * 32 + ldk;
        cp_async16(sA + bf * TBUF + soff,
                   Hb + (size_t)(m0 + ldr) * HH + k0);
        cp_async16(sA + bf * TBUF + soff + 64 * TROW,
                   Hb + (size_t)(m0 + ldr + 64) * HH + k0);
        cp_async16(sB + bf * TBUF + soff,
                   Wb + (size_t)(n0 + ldr) * HH + k0);
        cp_async16(sB + bf * TBUF + soff + 64 * TROW,
                   Wb + (size_t)(n0 + ldr + 64) * HH + k0);
        asm volatile("cp.async.commit_group;" ::: "memory");
    };

    issue(0, 0);

    // ldmatrix lane addressing (within warp tile)
    const int a_row = (lid & 15);          // + mt*16 + wm*32
    const int a_kh  = (lid >> 4) << 3;     // 0 or 8
    const int b_j   = lid >> 3;            // matrix id 0..3
    const int b_row = ((b_j >> 1) << 3) + (lid & 7);   // + nt16*16 + wn*64
    const int b_kh  = (b_j & 1) << 3;

    for (int c = 0; c < 16; c++) {
        const int bf = c & 1;
        if (c < 15) issue(c + 1, bf ^ 1);
        if (c < 15) asm volatile("cp.async.wait_group 1;" ::: "memory");
        else        asm volatile("cp.async.wait_group 0;" ::: "memory");
        __syncthreads();

        const uint32_t ab = sA + bf * TBUF;
        const uint32_t bb = sB + bf * TBUF;
#pragma unroll
        for (int ks = 0; ks < 32; ks += 16) {
            uint32_t afr[2][4];
#pragma unroll
            for (int mt = 0; mt < 2; mt++) {
                uint32_t addr = ab + (uint32_t)(wm * 32 + mt * 16 + a_row) * TROW
                              + (uint32_t)(ks + a_kh) * 2;
                LDM_X4(afr[mt][0], afr[mt][1], afr[mt][2], afr[mt][3], addr);
            }
#pragma unroll
            for (int nt16 = 0; nt16 < 4; nt16++) {
                uint32_t b0, b1, b2, b3;
                uint32_t addr = bb + (uint32_t)(wn * 64 + nt16 * 16 + b_row) * TROW
                              + (uint32_t)(ks + b_kh) * 2;
                LDM_X4(b0, b1, b2, b3, addr);
#pragma unroll
                for (int mt = 0; mt < 2; mt++) {
                    MMA_BF16(acc[mt][nt16 * 2 + 0], afr[mt], b0, b1);
                    MMA_BF16(acc[mt][nt16 * 2 + 1], afr[mt], b2, b3);
                }
            }
        }
        __syncthreads();
    }

    // epilogue: c0,c1 -> (row, col..col+1); c2,c3 -> (row+8, col..col+1)
    const int erow = lid >> 2;
    const int ecol = (lid & 3) << 1;
#pragma unroll
    for (int mt = 0; mt < 2; mt++) {
        const int row = m0 + wm * 32 + mt * 16 + erow;
#pragma unroll
        for (int nt = 0; nt < 8; nt++) {
            const int col = n0 + wn * 64 + nt * 8 + ecol;
            const float bv0 = b_out[col], bv1 = b_out[col + 1];
            float2 v0 = { acc[mt][nt][0] + bv0, acc[mt][nt][1] + bv1 };
            float2 v1 = { acc[mt][nt][2] + bv0, acc[mt][nt][3] + bv1 };
            *(float2*)&logits[(size_t)row * VV + col] = v0;
            *(float2*)&logits[(size_t)(row + 8) * VV + col] = v1;
        }
    }
}

// ------------------------- row softmax over V --------------------------------
__global__ __launch_bounds__(256)
void softmax_kernel(const float* __restrict__ L, float* __restrict__ out) {
    int r = blockIdx.x;
    int tid = threadIdx.x;
    const float* row = L + (size_t)r * VV;

    float m = -3.0e38f, s = 0.f;
    for (int v = tid; v < VV; v += 256) {
        float x = row[v];
        if (x > m) { s *= expf(m - x); m = x; }
        s += expf(x - m);
    }
    __shared__ float sm[256], ss[256];
    sm[tid] = m; ss[tid] = s;
    __syncthreads();
    for (int off = 128; off; off >>= 1) {
        if (tid < off) {
            float m2 = sm[tid + off], s2 = ss[tid + off];
            float M = fmaxf(sm[tid], m2);
            ss[tid] = ss[tid] * expf(sm[tid] - M) + s2 * expf(m2 - M);
            sm[tid] = M;
        }
        __syncthreads();
    }
    float M = sm[0];
    float inv = 1.f / ss[0];
    float* orow = out + (size_t)r * VV;
    for (int v = tid; v < VV; v += 256) {
        orow[v] = expf(row[v] - M) * inv;
    }
}

__global__ void copy_h1_kernel(const float* __restrict__ src, float* __restrict__ dst) {
    int i = blockIdx.x * blockDim.x + threadIdx.x;
    if (i < BB * HH) dst[i] = src[i];
}

// ------------------------- host launcher -------------------------------------
static float* sym_f(const void* sym) {
    void* p = nullptr; cudaGetSymbolAddress(&p, sym); return (float*)p;
}
static int* sym_i(const void* sym) {
    void* p = nullptr; cudaGetSymbolAddress(&p, sym); return (int*)p;
}
static unsigned* sym_u(const void* sym) {
    void* p = nullptr; cudaGetSymbolAddress(&p, sym); return (unsigned*)p;
}
static __nv_bfloat16* sym_b(const void* sym) {
    void* p = nullptr; cudaGetSymbolAddress(&p, sym); return (__nv_bfloat16*)p;
}

extern "C" void kernel_launch(void* const* d_in, const int* in_sizes, int n_in,
                              void* d_out, int out_size) {
    const int*   inputs  = (const int*)d_in[0];
    const float* hiddens = (const float*)d_in[1];
    const int*   targets = (const int*)d_in[2];
    const float* emb   = (const float*)d_in[4];
    const float* W_ih1 = (const float*)d_in[5];
    const float* W_hh1 = (const float*)d_in[6];
    const float* b_ih1 = (const float*)d_in[7];
    const float* b_hh1 = (const float*)d_in[8];
    const float* W_ih2 = (const float*)d_in[9];
    const float* W_hh2 = (const float*)d_in[10];
    const float* b_ih2 = (const float*)d_in[11];
    const float* b_hh2 = (const float*)d_in[12];
    const float* W_out = (const float*)d_in[13];
    const float* b_out = (const float*)d_in[14];
    float* out = (float*)d_out;

    float* X1 = sym_f(g_X1);
    float* X2 = sym_f(g_X2);
    float* H1 = sym_f(g_H1);
    float* H2 = sym_f(g_H2);
    float* LG = sym_f(g_logits);
    int*   TK = sym_i(g_tok);
    unsigned* BAR = sym_u(g_bar);
    __nv_bfloat16* Wb = sym_b(g_Wb);
    __nv_bfloat16* Hb = sym_b(g_Hb);

    // 1) init
    init_kernel<<<(BB * HH + 255) / 256, 256>>>(inputs, targets, hiddens);

    // 1b) W_out -> bf16 (independent of everything else)
    cvt_bf16_kernel<<<(VV * HH / 2 + 255) / 256, 256>>>(W_out, Wb, VV * HH / 2);

    // 2) X1 = gather(emb, tok) @ W_ih1^T + biases
    gemm_nt_bias<<<dim3(G4 / 64, (TT * BB) / 64), 256>>>(
        emb, HH, TK, W_ih1, b_ih1, b_hh1, X1, TT * BB, G4, HH);

    // 3) layer-1 recurrence (persistent)
    lstm_persistent<<<NBLK, 256>>>(X1, W_hh1, H1, BAR + 0);

    // 4) X2 = H1[1..64] @ W_ih2^T + biases
    gemm_nt_bias<<<dim3(G4 / 64, (TT * BB) / 64), 256>>>(
        H1 + BB * HH, HH, nullptr, W_ih2, b_ih2, b_hh2, X2, TT * BB, G4, HH);

    // 5) layer-2 recurrence
    lstm_persistent<<<NBLK, 256>>>(X2, W_hh2, H2, BAR + 1);

    // 5b) h2 sequence -> bf16
    cvt_bf16_kernel<<<(TT * BB * HH / 2 + 255) / 256, 256>>>(
        H2 + BB * HH, Hb, TT * BB * HH / 2);

    // 6) logits = h2 @ W_out^T + b_out  via bf16 mma.sync tensor cores
    gemm_mma<<<dim3(VV / 128, (TT * BB) / 128), 256>>>(Hb, Wb, b_out, LG);

    // 7) softmax
    softmax_kernel<<<TT * BB, 256>>>(LG, out);

    // 8) final h1
    long long tbv = (long long)TT * BB * VV;
    if ((long long)out_size >= tbv + (long long)BB * HH) {
        copy_h1_kernel<<<(BB * HH + 255) / 256, 256>>>(H1 + (size_t)TT * BB * HH,
                                                       out + tbv);
    }
}

// round 10
// speedup vs baseline: 1.0041x; 1.0028x over previous
#include <cuda_runtime.h>
#include <cuda_bf16.h>
#include <math.h>
#include <stdint.h>

#define BB 32
#define HH 512
#define G4 2048   // 4*HH
#define TT 64
#define VV 32000
#define NBLK 128  // persistent grid for LSTM

// ------------------------- device scratch (no allocs allowed) ----------------
__device__ float g_X1[TT * BB * G4];
__device__ float g_X2[TT * BB * G4];
__device__ float g_H1[(TT + 1) * BB * HH];
__device__ float g_H2[(TT + 1) * BB * HH];
__device__ float g_logits[(size_t)TT * BB * VV];  // 262 MB
__device__ int   g_tok[TT * BB];
__device__ unsigned g_bar[2];
__device__ __nv_bfloat16 g_Wb[(size_t)VV * HH];   // bf16 W_out
__device__ __nv_bfloat16 g_Hb[TT * BB * HH];      // bf16 h2 sequence

// ------------------------- init ---------------------------------------------
__global__ void init_kernel(const int* __restrict__ inputs,
                            const int* __restrict__ targets,
                            const float* __restrict__ hiddens) {
    int i = blockIdx.x * blockDim.x + threadIdx.x;
    if (i == 0) { g_bar[0] = 0u; g_bar[1] = 0u; }
    if (i < BB * HH) {
        g_H2[i] = 0.f;
        g_H1[i] = hiddens[i];
    }
    if (i < TT * BB) {
        int t = i / BB, b = i % BB;
        g_tok[i] = (t == 0) ? inputs[b] : targets[b * TT + (t - 1)];
    }
}

// ------------------------- f32 -> bf16 conversion ----------------------------
__global__ void cvt_bf16_kernel(const float* __restrict__ src,
                                __nv_bfloat16* __restrict__ dst, int n2) {
    int i = blockIdx.x * blockDim.x + threadIdx.x;
    if (i < n2) {
        float2 v = ((const float2*)src)[i];
        ((__nv_bfloat162*)dst)[i] = __float22bfloat162_rn(v);
    }
}

// ------------------------- fp32 GEMM (X1/X2 path) ----------------------------
__global__ __launch_bounds__(256)
void gemm_nt_bias(const float* __restrict__ A, int lda,
                  const int* __restrict__ rowidx,
                  const float* __restrict__ W,
                  const float* __restrict__ bias1,
                  const float* __restrict__ bias2,
                  float* __restrict__ C, int M, int N, int K) {
    __shared__ float As[16][68];
    __shared__ float Ws[16][68];

    int tid = threadIdx.x;
    int tx = tid & 15, ty = tid >> 4;
    int m0 = blockIdx.y * 64, n0 = blockIdx.x * 64;

    float acc[4][4];
#pragma unroll
    for (int i = 0; i < 4; i++)
#pragma unroll
        for (int j = 0; j < 4; j++) acc[i][j] = 0.f;

    int lr = tid >> 2;
    int lk = (tid & 3) << 2;
    int arow = m0 + lr;
    int asrc = rowidx ? rowidx[arow] : arow;
    const float* Ap = A + (size_t)asrc * lda + lk;
    const float* Wp = W + (size_t)(n0 + lr) * K + lk;

    for (int k0 = 0; k0 < K; k0 += 16) {
        float4 av = *(const float4*)(Ap + k0);
        float4 wv = *(const float4*)(Wp + k0);
        As[lk + 0][lr] = av.x; As[lk + 1][lr] = av.y;
        As[lk + 2][lr] = av.z; As[lk + 3][lr] = av.w;
        Ws[lk + 0][lr] = wv.x; Ws[lk + 1][lr] = wv.y;
        Ws[lk + 2][lr] = wv.z; Ws[lk + 3][lr] = wv.w;
        __syncthreads();
#pragma unroll
        for (int k = 0; k < 16; k++) {
            float4 a = *(const float4*)&As[k][ty * 4];
            float4 w = *(const float4*)&Ws[k][tx * 4];
            acc[0][0] += a.x * w.x; acc[0][1] += a.x * w.y; acc[0][2] += a.x * w.z; acc[0][3] += a.x * w.w;
            acc[1][0] += a.y * w.x; acc[1][1] += a.y * w.y; acc[1][2] += a.y * w.z; acc[1][3] += a.y * w.w;
            acc[2][0] += a.z * w.x; acc[2][1] += a.z * w.y; acc[2][2] += a.z * w.z; acc[2][3] += a.z * w.w;
            acc[3][0] += a.w * w.x; acc[3][1] += a.w * w.y; acc[3][2] += a.w * w.z; acc[3][3] += a.w * w.w;
        }
        __syncthreads();
    }

#pragma unroll
    for (int i = 0; i < 4; i++) {
        int cm = m0 + ty * 4 + i;
        float* Crow = C + (size_t)cm * N;
#pragma unroll
        for (int j = 0; j < 4; j++) {
            int cn = n0 + tx * 4 + j;
            float bv = bias1[cn] + (bias2 ? bias2[cn] : 0.f);
            Crow[cn] = acc[i][j] + bv;
        }
    }
}

// ------------------------- persistent LSTM layer -----------------------------
__global__ __launch_bounds__(256)
void lstm_persistent(const float* __restrict__ X,
                     const float* __restrict__ Wh,
                     float* __restrict__ H,
                     unsigned* __restrict__ bar) {
    __shared__ float Wt[HH][16];
    __shared__ float hs[64][33];
    __shared__ float gx[4][4][32];

    const int tid = threadIdx.x;
    const int j0 = blockIdx.x * 4;

#pragma unroll
    for (int r = 0; r < 16; r++) {
        int gate = r >> 2, jj = r & 3;
        const float* src = Wh + (size_t)(gate * HH + j0 + jj) * HH;
        for (int k = tid; k < HH; k += 256) Wt[k][r] = src[k];
    }

    const int b    = tid & 31;
    const int gate = (tid >> 5) & 3;
    const int jh   = tid >> 7;
    const int w2off = (gate << 2) + (jh << 1);

    const int fb = tid & 31;
    const int fj = (tid >> 5) & 3;
    float creg = 0.f;

    const int kkld = tid & 63;
    const int rbld = tid >> 6;

    __syncthreads();

    for (int t = 0; t < TT; t++) {
        const float* Hprev = H + (size_t)t * BB * HH;
        float acc0 = 0.f, acc1 = 0.f;

        for (int c = 0; c < 8; c++) {
            const int k0 = c * 64;
#pragma unroll
            for (int rep = 0; rep < 8; rep++) {
                int r = rbld + rep * 4;
                hs[kkld][r] = Hprev[r * HH + k0 + kkld];
            }
            __syncthreads();
#pragma unroll
            for (int kk = 0; kk < 64; kk++) {
                float hv = hs[kk][b];
                float2 w2 = *(const float2*)&Wt[k0 + kk][w2off];
                acc0 += hv * w2.x;
                acc1 += hv * w2.y;
            }
            __syncthreads();
        }

        gx[gate][(jh << 1) + 0][b] = acc0;
        gx[gate][(jh << 1) + 1][b] = acc1;
        __syncthreads();

        if (tid < 128) {
            const int j = j0 + fj;
            const float* xp = X + ((size_t)t * BB + fb) * G4;
            float gi = gx[0][fj][fb] + xp[0 * HH + j];
            float gf = gx[1][fj][fb] + xp[1 * HH + j];
            float gg = gx[2][fj][fb] + xp[2 * HH + j];
            float go = gx[3][fj][fb] + xp[3 * HH + j];

            float iv = 1.f / (1.f + expf(-gi));
            float fv = 1.f / (1.f + expf(-gf));
            float tv = tanhf(gg);
            float ov = 1.f / (1.f + expf(-go));

            creg = fv * creg + iv * tv;
            H[(size_t)(t + 1) * BB * HH + fb * HH + j] = ov * tanhf(creg);
        }

        __syncthreads();
        if (tid == 0) {
            __threadfence();
            atomicAdd(bar, 1u);
            unsigned target = (unsigned)(t + 1) * (unsigned)gridDim.x;
            while (*(volatile unsigned*)bar < target) { }
            __threadfence();
        }
        __syncthreads();
    }
}

// ------------------------- bf16 mma.sync output GEMM -------------------------
// logits[m][n] = sum_k Hb[m][k] * Wb[n][k] + b_out[n]
// Block tile 128(m) x 128(n), k-chunks of 32, cp.async double buffer.
// 8 warps: wm = wid&3 (m), wn = wid>>1&? -> wn = wid>>2 in {0,1}; warp = 32m x 64n.
#define LDM_X4(r0, r1, r2, r3, addr)                                           \
    asm volatile("ldmatrix.sync.aligned.m8n8.x4.shared.b16 {%0,%1,%2,%3}, [%4];" \
                 : "=r"(r0), "=r"(r1), "=r"(r2), "=r"(r3) : "r"(addr))

#define MMA_BF16(c, a, b0, b1)                                                 \
    asm volatile(                                                              \
        "mma.sync.aligned.m16n8k16.row.col.f32.bf16.bf16.f32 "                 \
        "{%0,%1,%2,%3}, {%4,%5,%6,%7}, {%8,%9}, {%0,%1,%2,%3};"                \
        : "+f"((c)[0]), "+f"((c)[1]), "+f"((c)[2]), "+f"((c)[3])               \
        : "r"((a)[0]), "r"((a)[1]), "r"((a)[2]), "r"((a)[3]),                  \
          "r"(b0), "r"(b1))

__device__ __forceinline__ uint32_t smem_u32(const void* p) {
    uint32_t a;
    asm("{ .reg .u64 t; cvta.to.shared.u64 t, %1; cvt.u32.u64 %0, t; }"
        : "=r"(a) : "l"(p));
    return a;
}
__device__ __forceinline__ void cp_async16(uint32_t s, const void* g) {
    asm volatile("cp.async.cg.shared.global [%0], [%1], 16;"
                 :: "r"(s), "l"(g) : "memory");
}

#define TROW 80   // padded SMEM row: 40 bf16 = 80 B (conflict-free for ldmatrix)
#define TBUF (128 * TROW)

__global__ __launch_bounds__(256)
void gemm_mma(const __nv_bfloat16* __restrict__ Hb,
              const __nv_bfloat16* __restrict__ Wb,
              const float* __restrict__ b_out,
              float* __restrict__ logits) {
    __shared__ __align__(16) char As[2 * TBUF];
    __shared__ __align__(16) char Bs[2 * TBUF];

    const int tid = threadIdx.x;
    const int lid = tid & 31, wid = tid >> 5;
    const int wm = wid & 3;        // 0..3 -> m offset wm*32
    const int wn = wid >> 2;       // 0..1 -> n offset wn*64
    const int m0 = blockIdx.y * 128;   // seq rows
    const int n0 = blockIdx.x * 128;   // vocab cols

    const uint32_t sA = smem_u32(As);
    const uint32_t sB = smem_u32(Bs);

    // per-thread global/shared load coords: row = tid/4 (+64), 8 bf16 at (tid%4)*8
    const int ldr = tid >> 2;
    const int ldk = (tid & 3) << 3;
    const uint32_t soff = (uint32_t)ldr * TROW + (uint32_t)ldk * 2;

    float acc[2][8][4];
#pragma unroll
    for (int a = 0; a < 2; a++)
#pragma unroll
        for (int b = 0; b < 8; b++)
#pragma unroll
            for (int c = 0; c < 4; c++) acc[a][b][c] = 0.f;

    // issue loads for chunk c into buffer bf
    auto issue = [&](int c, int bf) {
        const int k0 = c * 32 + ldk;
        cp_async16(sA + bf * TBUF + soff,
                   Hb + (size_t)(m0 + ldr) * HH + k0);
        cp_async16(sA + bf * TBUF + soff + 64 * TROW,
                   Hb + (size_t)(m0 + ldr + 64) * HH + k0);
        cp_async16(sB + bf * TBUF + soff,
                   Wb + (size_t)(n0 + ldr) * HH + k0);
        cp_async16(sB + bf * TBUF + soff + 64 * TROW,
                   Wb + (size_t)(n0 + ldr + 64) * HH + k0);
        asm volatile("cp.async.commit_group;" ::: "memory");
    };

    issue(0, 0);

    // ldmatrix lane addressing (within warp tile)
    const int a_row = (lid & 15);          // + mt*16 + wm*32
    const int a_kh  = (lid >> 4) << 3;     // 0 or 8
    const int b_j   = lid >> 3;            // matrix id 0..3
    const int b_row = ((b_j >> 1) << 3) + (lid & 7);   // + nt16*16 + wn*64
    const int b_kh  = (b_j & 1) << 3;

    for (int c = 0; c < 16; c++) {
        const int bf = c & 1;
        if (c < 15) issue(c + 1, bf ^ 1);
        if (c < 15) asm volatile("cp.async.wait_group 1;" ::: "memory");
        else        asm volatile("cp.async.wait_group 0;" ::: "memory");
        __syncthreads();

        const uint32_t ab = sA + bf * TBUF;
        const uint32_t bb = sB + bf * TBUF;
#pragma unroll
        for (int ks = 0; ks < 32; ks += 16) {
            uint32_t afr[2][4];
#pragma unroll
            for (int mt = 0; mt < 2; mt++) {
                uint32_t addr = ab + (uint32_t)(wm * 32 + mt * 16 + a_row) * TROW
                              + (uint32_t)(ks + a_kh) * 2;
                LDM_X4(afr[mt][0], afr[mt][1], afr[mt][2], afr[mt][3], addr);
            }
#pragma unroll
            for (int nt16 = 0; nt16 < 4; nt16++) {
                uint32_t b0, b1, b2, b3;
                uint32_t addr = bb + (uint32_t)(wn * 64 + nt16 * 16 + b_row) * TROW
                              + (uint32_t)(ks + b_kh) * 2;
                LDM_X4(b0, b1, b2, b3, addr);
#pragma unroll
                for (int mt = 0; mt < 2; mt++) {
                    MMA_BF16(acc[mt][nt16 * 2 + 0], afr[mt], b0, b1);
                    MMA_BF16(acc[mt][nt16 * 2 + 1], afr[mt], b2, b3);
                }
            }
        }
        __syncthreads();
    }

    // epilogue: c0,c1 -> (row, col..col+1); c2,c3 -> (row+8, col..col+1)
    const int erow = lid >> 2;
    const int ecol = (lid & 3) << 1;
#pragma unroll
    for (int mt = 0; mt < 2; mt++) {
        const int row = m0 + wm * 32 + mt * 16 + erow;
#pragma unroll
        for (int nt = 0; nt < 8; nt++) {
            const int col = n0 + wn * 64 + nt * 8 + ecol;
            const float bv0 = b_out[col], bv1 = b_out[col + 1];
            float2 v0 = { acc[mt][nt][0] + bv0, acc[mt][nt][1] + bv1 };
            float2 v1 = { acc[mt][nt][2] + bv0, acc[mt][nt][3] + bv1 };
            *(float2*)&logits[(size_t)row * VV + col] = v0;
            *(float2*)&logits[(size_t)(row + 8) * VV + col] = v1;
        }
    }
}

// ------------------------- row softmax over V --------------------------------
__global__ __launch_bounds__(256)
void softmax_kernel(const float* __restrict__ L, float* __restrict__ out) {
    int r = blockIdx.x;
    int tid = threadIdx.x;
    const float* row = L + (size_t)r * VV;

    float m = -3.0e38f, s = 0.f;
    for (int v = tid; v < VV; v += 256) {
        float x = row[v];
        if (x > m) { s *= expf(m - x); m = x; }
        s += expf(x - m);
    }
    __shared__ float sm[256], ss[256];
    sm[tid] = m; ss[tid] = s;
    __syncthreads();
    for (int off = 128; off; off >>= 1) {
        if (tid < off) {
            float m2 = sm[tid + off], s2 = ss[tid + off];
            float M = fmaxf(sm[tid], m2);
            ss[tid] = ss[tid] * expf(sm[tid] - M) + s2 * expf(m2 - M);
            sm[tid] = M;
        }
        __syncthreads();
    }
    float M = sm[0];
    float inv = 1.f / ss[0];
    float* orow = out + (size_t)r * VV;
    for (int v = tid; v < VV; v += 256) {
        orow[v] = expf(row[v] - M) * inv;
    }
}

__global__ void copy_h1_kernel(const float* __restrict__ src, float* __restrict__ dst) {
    int i = blockIdx.x * blockDim.x + threadIdx.x;
    if (i < BB * HH) dst[i] = src[i];
}

// ------------------------- host launcher -------------------------------------
static float* sym_f(const void* sym) {
    void* p = nullptr; cudaGetSymbolAddress(&p, sym); return (float*)p;
}
static int* sym_i(const void* sym) {
    void* p = nullptr; cudaGetSymbolAddress(&p, sym); return (int*)p;
}
static unsigned* sym_u(const void* sym) {
    void* p = nullptr; cudaGetSymbolAddress(&p, sym); return (unsigned*)p;
}
static __nv_bfloat16* sym_b(const void* sym) {
    void* p = nullptr; cudaGetSymbolAddress(&p, sym); return (__nv_bfloat16*)p;
}

extern "C" void kernel_launch(void* const* d_in, const int* in_sizes, int n_in,
                              void* d_out, int out_size) {
    const int*   inputs  = (const int*)d_in[0];
    const float* hiddens = (const float*)d_in[1];
    const int*   targets = (const int*)d_in[2];
    const float* emb   = (const float*)d_in[4];
    const float* W_ih1 = (const float*)d_in[5];
    const float* W_hh1 = (const float*)d_in[6];
    const float* b_ih1 = (const float*)d_in[7];
    const float* b_hh1 = (const float*)d_in[8];
    const float* W_ih2 = (const float*)d_in[9];
    const float* W_hh2 = (const float*)d_in[10];
    const float* b_ih2 = (const float*)d_in[11];
    const float* b_hh2 = (const float*)d_in[12];
    const float* W_out = (const float*)d_in[13];
    const float* b_out = (const float*)d_in[14];
    float* out = (float*)d_out;

    float* X1 = sym_f(g_X1);
    float* X2 = sym_f(g_X2);
    float* H1 = sym_f(g_H1);
    float* H2 = sym_f(g_H2);
    float* LG = sym_f(g_logits);
    int*   TK = sym_i(g_tok);
    unsigned* BAR = sym_u(g_bar);
    __nv_bfloat16* Wb = sym_b(g_Wb);
    __nv_bfloat16* Hb = sym_b(g_Hb);

    // 1) init
    init_kernel<<<(BB * HH + 255) / 256, 256>>>(inputs, targets, hiddens);

    // 1b) W_out -> bf16 (independent of everything else)
    cvt_bf16_kernel<<<(VV * HH / 2 + 255) / 256, 256>>>(W_out, Wb, VV * HH / 2);

    // 2) X1 = gather(emb, tok) @ W_ih1^T + biases
    gemm_nt_bias<<<dim3(G4 / 64, (TT * BB) / 64), 256>>>(
        emb, HH, TK, W_ih1, b_ih1, b_hh1, X1, TT * BB, G4, HH);

    // 3) layer-1 recurrence (persistent)
    lstm_persistent<<<NBLK, 256>>>(X1, W_hh1, H1, BAR + 0);

    // 4) X2 = H1[1..64] @ W_ih2^T + biases
    gemm_nt_bias<<<dim3(G4 / 64, (TT * BB) / 64), 256>>>(
        H1 + BB * HH, HH, nullptr, W_ih2, b_ih2, b_hh2, X2, TT * BB, G4, HH);

    // 5) layer-2 recurrence
    lstm_persistent<<<NBLK, 256>>>(X2, W_hh2, H2, BAR + 1);

    // 5b) h2 sequence -> bf16
    cvt_bf16_kernel<<<(TT * BB * HH / 2 + 255) / 256, 256>>>(
        H2 + BB * HH, Hb, TT * BB * HH / 2);

    // 6) logits = h2 @ W_out^T + b_out  via bf16 mma.sync tensor cores
    gemm_mma<<<dim3(VV / 128, (TT * BB) / 128), 256>>>(Hb, Wb, b_out, LG);

    // 7) softmax
    softmax_kernel<<<TT * BB, 256>>>(LG, out);

    // 8) final h1
    long long tbv = (long long)TT * BB * VV;
    if ((long long)out_size >= tbv + (long long)BB * HH) {
        copy_h1_kernel<<<(BB * HH + 255) / 256, 256>>>(H1 + (size_t)TT * BB * HH,
                                                       out + tbv);
    }
}